// round 15
// baseline (speedup 1.0000x reference)
#include <cuda_runtime.h>
#include <cuda_fp16.h>
#include <mma.h>
#include <cstdint>

using namespace nvcuda;

#define BB 32
#define SS 2048
#define DD 1024
#define MM (BB * SS)

// ---------------- scratch (static device globals; no runtime alloc) ------
__device__ float  g_scores[BB * SS];
__device__ float  g_uq[BB * DD];
__device__ __half g_Whi[DD * DD];
__device__ __half g_Wlo[DD * DD];          // unscaled residual (subnormals ok)

// ---------------- cp.async helpers ---------------------------------------
__device__ __forceinline__ uint32_t smem_u32(const void* p) {
    uint32_t a;
    asm("{ .reg .u64 t; cvta.to.shared.u64 t, %1; cvt.u32.u64 %0, t; }"
        : "=r"(a) : "l"(p));
    return a;
}
__device__ __forceinline__ void cp16(uint32_t dst, const void* src) {
    asm volatile("cp.async.cg.shared.global [%0], [%1], 16;" :: "r"(dst), "l"(src) : "memory");
}
__device__ __forceinline__ void cp_commit() {
    asm volatile("cp.async.commit_group;" ::: "memory");
}
template <int N> __device__ __forceinline__ void cp_wait() {
    asm volatile("cp.async.wait_group %0;" :: "n"(N) : "memory");
}

// ---------------- K_a: W split + uq + score zero (fused) ------------------
__global__ void __launch_bounds__(256) prep_kernel(const float* __restrict__ W,
                                                   const float* __restrict__ U,
                                                   const float* __restrict__ rs) {
    int gtid = blockIdx.x * 256 + threadIdx.x;   // 0 .. 1048575

    if (gtid < BB * SS) g_scores[gtid] = 0.0f;

    if (gtid < DD * DD / 4) {                    // W split: 4 elems per thread
        int i = gtid * 4;
        float4 v = *(const float4*)(W + i);
        __half2 h01 = __floats2half2_rn(v.x, v.y);
        __half2 h23 = __floats2half2_rn(v.z, v.w);
        float2 b01 = __half22float2(h01), b23 = __half22float2(h23);
        __half2 l01 = __floats2half2_rn(v.x - b01.x, v.y - b01.y);
        __half2 l23 = __floats2half2_rn(v.z - b23.x, v.w - b23.y);
        *(__half2*)(g_Whi + i)     = h01;
        *(__half2*)(g_Whi + i + 2) = h23;
        *(__half2*)(g_Wlo + i)     = l01;
        *(__half2*)(g_Wlo + i + 2) = l23;
    }

    int w = gtid >> 5;                           // uq: warp per output
    int lane = gtid & 31;
    if (w < BB * DD) {
        int b = w >> 10;
        int d = w & 1023;
        const float* Urow = U + (size_t)d * DD;
        const float* rb = rs + (size_t)b * DD;
        float acc = 0.0f;
        #pragma unroll 8
        for (int e = lane; e < DD; e += 32) acc += Urow[e] * rb[e];
        #pragma unroll
        for (int o = 16; o > 0; o >>= 1) acc += __shfl_xor_sync(0xffffffffu, acc, o);
        if (lane == 0) g_uq[w] = acc;
    }
}

// ---------------- K_c: fp16x3 GEMM + relu + score (unchanged from R14) ----
// TWO CTAs PER SM. CTA: 128 threads, tile 128m x 128n, BK=32, double-buffered.
// 4 warps = 2(m) x 2(n); warp tile 64m x 64n. A split in-kernel.
#define LDH 40
#define ROWB (LDH * 2)
#define A_TILE_B (128 * ROWB)
#define STAGE_B (4 * A_TILE_B)
#define SMEM_DYN (2 * STAGE_B)
#define BPST_B (32 * ROWB)
#define BPST_H (32 * DD)

__device__ __forceinline__ void cp_b(int p, uint32_t dstA,
                                     const __half* sWhi, const __half* sWlo) {
    if (p < 4)
        cp16(dstA + 2 * A_TILE_B + p * BPST_B, sWhi + (size_t)p * BPST_H);
    else
        cp16(dstA + 3 * A_TILE_B + (p - 4) * BPST_B, sWlo + (size_t)(p - 4) * BPST_H);
}

__device__ __forceinline__ void cvt_sts(float4 v, unsigned char* smemc, uint32_t off) {
    __half2 hA = __floats2half2_rn(v.x, v.y);
    __half2 hB = __floats2half2_rn(v.z, v.w);
    float2 fA = __half22float2(hA), fB = __half22float2(hB);
    __half2 lA = __floats2half2_rn(v.x - fA.x, v.y - fA.y);
    __half2 lB = __floats2half2_rn(v.z - fB.x, v.w - fB.y);
    uint2 hv, lv;
    hv.x = *reinterpret_cast<uint32_t*>(&hA);
    hv.y = *reinterpret_cast<uint32_t*>(&hB);
    lv.x = *reinterpret_cast<uint32_t*>(&lA);
    lv.y = *reinterpret_cast<uint32_t*>(&lB);
    *(uint2*)(smemc + off)            = hv;
    *(uint2*)(smemc + off + A_TILE_B) = lv;
}

__global__ void __launch_bounds__(128, 2) gemm_score_kernel(const float* __restrict__ h,
                                                            const float* __restrict__ rs) {
    extern __shared__ __align__(16) unsigned char dyn[];
    __shared__ float uqs[128], qs[128];

    const int tid = threadIdx.x;
    const int wid = tid >> 5;
    const int wm  = wid & 1;
    const int wn  = wid >> 1;
    const int m0  = blockIdx.y * 128;
    const int n0  = blockIdx.x * 128;
    const int b   = blockIdx.y >> 4;

    uqs[tid] = g_uq[b * DD + n0 + tid];
    qs[tid]  = rs[(size_t)b * DD + n0 + tid];

    const uint32_t sbase = smem_u32(dyn);

    const int arow = tid >> 3;
    const int acol = (tid & 7) * 4;
    const float* pA = h + (size_t)(m0 + arow) * DD + acol;
    const uint32_t aoff = arow * ROWB + acol * 2;

    const int brow = tid >> 2;
    const int bseg = tid & 3;
    const __half* pWhi = g_Whi + (size_t)(n0 + brow) * DD + bseg * 8;
    const __half* pWlo = g_Wlo + (size_t)(n0 + brow) * DD + bseg * 8;
    const uint32_t boff = brow * ROWB + bseg * 16;

    wmma::fragment<wmma::accumulator, 16, 16, 16, float> acc[4][4];
    #pragma unroll
    for (int i = 0; i < 4; i++)
        #pragma unroll
        for (int j = 0; j < 4; j++)
            wmma::fill_fragment(acc[i][j], 0.0f);

    {
        unsigned char* smemc = dyn;
        #pragma unroll
        for (int i = 0; i < 8; i++) {
            float4 v = *(const float4*)(pA + (size_t)(i * 16) * DD);
            cvt_sts(v, smemc, aoff + i * 16 * ROWB);
        }
        const uint32_t d0 = sbase + boff;
        #pragma unroll
        for (int p = 0; p < 8; p++) cp_b(p, d0, pWhi, pWlo);
        cp_commit();
    }

    #pragma unroll 1
    for (int s = 0; s < 32; s++) {
        cp_wait<0>();
        __syncthreads();

        const __half* Ahi = (const __half*)(dyn + (s & 1) * STAGE_B);
        const __half* Bhi = Ahi + 2 * 128 * LDH;

        const int nk0 = (s + 1) * 32;
        unsigned char* nsm = dyn + ((s + 1) & 1) * STAGE_B;
        const uint32_t ndst = sbase + ((s + 1) & 1) * STAGE_B + boff;
        const float* nA = pA + nk0;
        const __half* nWhi = pWhi + nk0;
        const __half* nWlo = pWlo + nk0;
        const bool more = (s + 1 < 32);

        float4 av[4];

        #pragma unroll
        for (int ks = 0; ks < 2; ks++) {
            wmma::fragment<wmma::matrix_b, 16, 16, 16, __half, wmma::col_major> bh[4], bl[4];
            #pragma unroll
            for (int j = 0; j < 4; j++) {
                const __half* pb = Bhi + (wn * 64 + j * 16) * LDH + ks * 16;
                wmma::load_matrix_sync(bh[j], pb, LDH);
                wmma::load_matrix_sync(bl[j], pb + 128 * LDH, LDH);
            }
            #pragma unroll
            for (int i = 0; i < 4; i++) {
                const int g = ks * 4 + i;
                if (more) {
                    if (g == 0 || g == 4) {
                        const int base = (g == 0) ? 0 : 4;
                        #pragma unroll
                        for (int q = 0; q < 4; q++)
                            av[q] = *(const float4*)(nA + (size_t)((base + q) * 16) * DD);
                    } else if (g == 1 || g == 2 || g == 5 || g == 6) {
                        const int p = (g <= 2) ? (g - 1) * 2 : (g - 3) * 2;
                        cp_b(p,     ndst, nWhi, nWlo);
                        cp_b(p + 1, ndst, nWhi, nWlo);
                        if (g == 6) cp_commit();
                    } else {
                        const int base = (g == 3) ? 0 : 4;
                        #pragma unroll
                        for (int q = 0; q < 4; q++)
                            cvt_sts(av[q], nsm, aoff + (base + q) * 16 * ROWB);
                    }
                }
                wmma::fragment<wmma::matrix_a, 16, 16, 16, __half, wmma::row_major> ah, al;
                const __half* pa = Ahi + (wm * 64 + i * 16) * LDH + ks * 16;
                wmma::load_matrix_sync(ah, pa, LDH);
                wmma::load_matrix_sync(al, pa + 128 * LDH, LDH);
                #pragma unroll
                for (int j = 0; j < 4; j++)
                    wmma::mma_sync(acc[i][j], ah, bh[j], acc[i][j]);
                #pragma unroll
                for (int j = 0; j < 4; j++)
                    wmma::mma_sync(acc[i][j], ah, bl[j], acc[i][j]);
                #pragma unroll
                for (int j = 0; j < 4; j++)
                    wmma::mma_sync(acc[i][j], al, bh[j], acc[i][j]);
            }
        }
    }
    __syncthreads();

    float* Es = (float*)dyn;
    #pragma unroll
    for (int i = 0; i < 4; i++)
        #pragma unroll
        for (int j = 0; j < 4; j++)
            wmma::store_matrix_sync(Es + (wm * 64 + i * 16) * 132 + (wn * 64 + j * 16),
                                    acc[i][j], 132, wmma::mem_row_major);
    __syncthreads();

    float partial = 0.0f;
    const float* row = Es + tid * 132;
    #pragma unroll 16
    for (int c = 0; c < 128; c++) {
        float v = row[c] + uqs[c];
        partial += fmaxf(v, 0.0f) * qs[c];
    }
    atomicAdd(&g_scores[m0 + tid], partial);
}

// ---------------- K_d: fused softmax + matched ----------------------------
// Grid (4, BB) x 256. Each CTA: softmax of its batch in smem (redundant x4);
// quarter 0 writes weights; all CTAs compute 256 matched columns, direct store.
__global__ void __launch_bounds__(256) softmax_matched_kernel(const float* __restrict__ h,
                                                              float* __restrict__ out) {
    const int b   = blockIdx.y;
    const int qtr = blockIdx.x;              // 0..3, column quarter
    const int tid = threadIdx.x;
    __shared__ float ws[SS];
    __shared__ float red[256];

    const float* sc = g_scores + (size_t)b * SS;

    float mx = -1e30f;
    #pragma unroll
    for (int i = tid; i < SS; i += 256) {
        float v = sc[i];
        ws[i] = v;
        mx = fmaxf(mx, v);
    }
    red[tid] = mx; __syncthreads();
    for (int s = 128; s > 0; s >>= 1) {
        if (tid < s) red[tid] = fmaxf(red[tid], red[tid + s]);
        __syncthreads();
    }
    mx = red[0]; __syncthreads();

    float sum = 0.0f;
    #pragma unroll
    for (int i = tid; i < SS; i += 256) {
        float e = expf(ws[i] - mx);
        ws[i] = e;
        sum += e;
    }
    red[tid] = sum; __syncthreads();
    for (int s = 128; s > 0; s >>= 1) {
        if (tid < s) red[tid] += red[tid + s];
        __syncthreads();
    }
    const float inv = 1.0f / red[0];
    __syncthreads();
    #pragma unroll
    for (int i = tid; i < SS; i += 256) ws[i] *= inv;
    __syncthreads();

    if (qtr == 0) {                          // write normalized weights once
        float* wout = out + BB * DD + (size_t)b * SS;
        #pragma unroll
        for (int i = tid; i < SS; i += 256) wout[i] = ws[i];
    }

    // matched for columns [qtr*256, qtr*256+256)
    const int d = qtr * 256 + tid;
    const float* hb = h + (size_t)b * SS * DD + d;
    float acc = 0.0f;
    #pragma unroll 8
    for (int s = 0; s < SS; s++) acc += hb[(size_t)s * DD] * ws[s];
    out[(size_t)b * DD + d] = acc;
}

// ---------------------------------------------------------------------------
extern "C" void kernel_launch(void* const* d_in, const int* in_sizes, int n_in,
                              void* d_out, int out_size) {
    const float* h  = (const float*)d_in[0];
    const float* rs = (const float*)d_in[1];
    const float* W  = (const float*)d_in[2];
    const float* U  = (const float*)d_in[3];
    float* out = (float*)d_out;

    cudaFuncSetAttribute(gemm_score_kernel,
                         cudaFuncAttributeMaxDynamicSharedMemorySize, SMEM_DYN);

    prep_kernel<<<4096, 256>>>(W, U, rs);
    gemm_score_kernel<<<dim3(8, 512), 128, SMEM_DYN>>>(h, rs);
    softmax_matched_kernel<<<dim3(4, BB), 256>>>(h, out);
}

// round 16
// speedup vs baseline: 1.1274x; 1.1274x over previous
#include <cuda_runtime.h>
#include <cuda_fp16.h>
#include <mma.h>
#include <cstdint>

using namespace nvcuda;

#define BB 32
#define SS 2048
#define DD 1024
#define MM (BB * SS)

// ---------------- scratch (static device globals; no runtime alloc) ------
__device__ float  g_scores[BB * SS];
__device__ float  g_uq[BB * DD];
__device__ __half g_Whi[DD * DD];
__device__ __half g_Wlo[DD * DD];          // unscaled residual (subnormals ok)

// ---------------- cp.async helpers ---------------------------------------
__device__ __forceinline__ uint32_t smem_u32(const void* p) {
    uint32_t a;
    asm("{ .reg .u64 t; cvta.to.shared.u64 t, %1; cvt.u32.u64 %0, t; }"
        : "=r"(a) : "l"(p));
    return a;
}
__device__ __forceinline__ void cp16(uint32_t dst, const void* src) {
    asm volatile("cp.async.cg.shared.global [%0], [%1], 16;" :: "r"(dst), "l"(src) : "memory");
}
__device__ __forceinline__ void cp_commit() {
    asm volatile("cp.async.commit_group;" ::: "memory");
}
template <int N> __device__ __forceinline__ void cp_wait() {
    asm volatile("cp.async.wait_group %0;" :: "n"(N) : "memory");
}

// ---------------- K_a: W split + uq + zero scores + zero matched ----------
__global__ void __launch_bounds__(256) prep_kernel(const float* __restrict__ W,
                                                   const float* __restrict__ U,
                                                   const float* __restrict__ rs,
                                                   float* __restrict__ out) {
    int gtid = blockIdx.x * 256 + threadIdx.x;   // 0 .. 1048575

    if (gtid < BB * SS) g_scores[gtid] = 0.0f;
    if (gtid < BB * DD) out[gtid] = 0.0f;        // matched accumulators

    if (gtid < DD * DD / 4) {                    // W split: 4 elems per thread
        int i = gtid * 4;
        float4 v = *(const float4*)(W + i);
        __half2 h01 = __floats2half2_rn(v.x, v.y);
        __half2 h23 = __floats2half2_rn(v.z, v.w);
        float2 b01 = __half22float2(h01), b23 = __half22float2(h23);
        __half2 l01 = __floats2half2_rn(v.x - b01.x, v.y - b01.y);
        __half2 l23 = __floats2half2_rn(v.z - b23.x, v.w - b23.y);
        *(__half2*)(g_Whi + i)     = h01;
        *(__half2*)(g_Whi + i + 2) = h23;
        *(__half2*)(g_Wlo + i)     = l01;
        *(__half2*)(g_Wlo + i + 2) = l23;
    }

    int w = gtid >> 5;                           // uq: warp per output
    int lane = gtid & 31;
    if (w < BB * DD) {
        int b = w >> 10;
        int d = w & 1023;
        const float* Urow = U + (size_t)d * DD;
        const float* rb = rs + (size_t)b * DD;
        float acc = 0.0f;
        #pragma unroll 8
        for (int e = lane; e < DD; e += 32) acc += Urow[e] * rb[e];
        #pragma unroll
        for (int o = 16; o > 0; o >>= 1) acc += __shfl_xor_sync(0xffffffffu, acc, o);
        if (lane == 0) g_uq[w] = acc;
    }
}

// ---------------- K_c: fp16x3 GEMM + relu + score (unchanged) -------------
// TWO CTAs PER SM. CTA: 128 threads, tile 128m x 128n, BK=32, double-buffered.
// 4 warps = 2(m) x 2(n); warp tile 64m x 64n. A split in-kernel.
#define LDH 40
#define ROWB (LDH * 2)
#define A_TILE_B (128 * ROWB)
#define STAGE_B (4 * A_TILE_B)
#define SMEM_DYN (2 * STAGE_B)
#define BPST_B (32 * ROWB)
#define BPST_H (32 * DD)

__device__ __forceinline__ void cp_b(int p, uint32_t dstA,
                                     const __half* sWhi, const __half* sWlo) {
    if (p < 4)
        cp16(dstA + 2 * A_TILE_B + p * BPST_B, sWhi + (size_t)p * BPST_H);
    else
        cp16(dstA + 3 * A_TILE_B + (p - 4) * BPST_B, sWlo + (size_t)(p - 4) * BPST_H);
}

__device__ __forceinline__ void cvt_sts(float4 v, unsigned char* smemc, uint32_t off) {
    __half2 hA = __floats2half2_rn(v.x, v.y);
    __half2 hB = __floats2half2_rn(v.z, v.w);
    float2 fA = __half22float2(hA), fB = __half22float2(hB);
    __half2 lA = __floats2half2_rn(v.x - fA.x, v.y - fA.y);
    __half2 lB = __floats2half2_rn(v.z - fB.x, v.w - fB.y);
    uint2 hv, lv;
    hv.x = *reinterpret_cast<uint32_t*>(&hA);
    hv.y = *reinterpret_cast<uint32_t*>(&hB);
    lv.x = *reinterpret_cast<uint32_t*>(&lA);
    lv.y = *reinterpret_cast<uint32_t*>(&lB);
    *(uint2*)(smemc + off)            = hv;
    *(uint2*)(smemc + off + A_TILE_B) = lv;
}

__global__ void __launch_bounds__(128, 2) gemm_score_kernel(const float* __restrict__ h,
                                                            const float* __restrict__ rs) {
    extern __shared__ __align__(16) unsigned char dyn[];
    __shared__ float uqs[128], qs[128];

    const int tid = threadIdx.x;
    const int wid = tid >> 5;
    const int wm  = wid & 1;
    const int wn  = wid >> 1;
    const int m0  = blockIdx.y * 128;
    const int n0  = blockIdx.x * 128;
    const int b   = blockIdx.y >> 4;

    uqs[tid] = g_uq[b * DD + n0 + tid];
    qs[tid]  = rs[(size_t)b * DD + n0 + tid];

    const uint32_t sbase = smem_u32(dyn);

    const int arow = tid >> 3;
    const int acol = (tid & 7) * 4;
    const float* pA = h + (size_t)(m0 + arow) * DD + acol;
    const uint32_t aoff = arow * ROWB + acol * 2;

    const int brow = tid >> 2;
    const int bseg = tid & 3;
    const __half* pWhi = g_Whi + (size_t)(n0 + brow) * DD + bseg * 8;
    const __half* pWlo = g_Wlo + (size_t)(n0 + brow) * DD + bseg * 8;
    const uint32_t boff = brow * ROWB + bseg * 16;

    wmma::fragment<wmma::accumulator, 16, 16, 16, float> acc[4][4];
    #pragma unroll
    for (int i = 0; i < 4; i++)
        #pragma unroll
        for (int j = 0; j < 4; j++)
            wmma::fill_fragment(acc[i][j], 0.0f);

    {
        unsigned char* smemc = dyn;
        #pragma unroll
        for (int i = 0; i < 8; i++) {
            float4 v = *(const float4*)(pA + (size_t)(i * 16) * DD);
            cvt_sts(v, smemc, aoff + i * 16 * ROWB);
        }
        const uint32_t d0 = sbase + boff;
        #pragma unroll
        for (int p = 0; p < 8; p++) cp_b(p, d0, pWhi, pWlo);
        cp_commit();
    }

    #pragma unroll 1
    for (int s = 0; s < 32; s++) {
        cp_wait<0>();
        __syncthreads();

        const __half* Ahi = (const __half*)(dyn + (s & 1) * STAGE_B);
        const __half* Bhi = Ahi + 2 * 128 * LDH;

        const int nk0 = (s + 1) * 32;
        unsigned char* nsm = dyn + ((s + 1) & 1) * STAGE_B;
        const uint32_t ndst = sbase + ((s + 1) & 1) * STAGE_B + boff;
        const float* nA = pA + nk0;
        const __half* nWhi = pWhi + nk0;
        const __half* nWlo = pWlo + nk0;
        const bool more = (s + 1 < 32);

        float4 av[4];

        #pragma unroll
        for (int ks = 0; ks < 2; ks++) {
            wmma::fragment<wmma::matrix_b, 16, 16, 16, __half, wmma::col_major> bh[4], bl[4];
            #pragma unroll
            for (int j = 0; j < 4; j++) {
                const __half* pb = Bhi + (wn * 64 + j * 16) * LDH + ks * 16;
                wmma::load_matrix_sync(bh[j], pb, LDH);
                wmma::load_matrix_sync(bl[j], pb + 128 * LDH, LDH);
            }
            #pragma unroll
            for (int i = 0; i < 4; i++) {
                const int g = ks * 4 + i;
                if (more) {
                    if (g == 0 || g == 4) {
                        const int base = (g == 0) ? 0 : 4;
                        #pragma unroll
                        for (int q = 0; q < 4; q++)
                            av[q] = *(const float4*)(nA + (size_t)((base + q) * 16) * DD);
                    } else if (g == 1 || g == 2 || g == 5 || g == 6) {
                        const int p = (g <= 2) ? (g - 1) * 2 : (g - 3) * 2;
                        cp_b(p,     ndst, nWhi, nWlo);
                        cp_b(p + 1, ndst, nWhi, nWlo);
                        if (g == 6) cp_commit();
                    } else {
                        const int base = (g == 3) ? 0 : 4;
                        #pragma unroll
                        for (int q = 0; q < 4; q++)
                            cvt_sts(av[q], nsm, aoff + (base + q) * 16 * ROWB);
                    }
                }
                wmma::fragment<wmma::matrix_a, 16, 16, 16, __half, wmma::row_major> ah, al;
                const __half* pa = Ahi + (wm * 64 + i * 16) * LDH + ks * 16;
                wmma::load_matrix_sync(ah, pa, LDH);
                wmma::load_matrix_sync(al, pa + 128 * LDH, LDH);
                #pragma unroll
                for (int j = 0; j < 4; j++)
                    wmma::mma_sync(acc[i][j], ah, bh[j], acc[i][j]);
                #pragma unroll
                for (int j = 0; j < 4; j++)
                    wmma::mma_sync(acc[i][j], ah, bl[j], acc[i][j]);
                #pragma unroll
                for (int j = 0; j < 4; j++)
                    wmma::mma_sync(acc[i][j], al, bh[j], acc[i][j]);
            }
        }
    }
    __syncthreads();

    float* Es = (float*)dyn;
    #pragma unroll
    for (int i = 0; i < 4; i++)
        #pragma unroll
        for (int j = 0; j < 4; j++)
            wmma::store_matrix_sync(Es + (wm * 64 + i * 16) * 132 + (wn * 64 + j * 16),
                                    acc[i][j], 132, wmma::mem_row_major);
    __syncthreads();

    float partial = 0.0f;
    const float* row = Es + tid * 132;
    #pragma unroll 16
    for (int c = 0; c < 128; c++) {
        float v = row[c] + uqs[c];
        partial += fmaxf(v, 0.0f) * qs[c];
    }
    atomicAdd(&g_scores[m0 + tid], partial);
}

// ---------------- K_d: softmax over S per batch (R14-proven) --------------
__global__ void __launch_bounds__(256) softmax_kernel(float* __restrict__ out) {
    const int b = blockIdx.x;
    const int tid = threadIdx.x;
    __shared__ float red[256];
    const float* sc = g_scores + (size_t)b * SS;
    float* wout = out + BB * DD + (size_t)b * SS;

    float mx = -1e30f;
    for (int i = tid; i < SS; i += 256) mx = fmaxf(mx, sc[i]);
    red[tid] = mx; __syncthreads();
    for (int s = 128; s > 0; s >>= 1) {
        if (tid < s) red[tid] = fmaxf(red[tid], red[tid + s]);
        __syncthreads();
    }
    mx = red[0]; __syncthreads();

    float sum = 0.0f;
    for (int i = tid; i < SS; i += 256) {
        float e = expf(sc[i] - mx);
        wout[i] = e;
        sum += e;
    }
    red[tid] = sum; __syncthreads();
    for (int s = 128; s > 0; s >>= 1) {
        if (tid < s) red[tid] += red[tid + s];
        __syncthreads();
    }
    float inv = 1.0f / red[0];
    for (int i = tid; i < SS; i += 256) wout[i] *= inv;
}

// ---------------- K_e: matched (R14-proven: 512 CTAs, float4) -------------
__global__ void __launch_bounds__(256) matched_kernel(const float* __restrict__ h,
                                                      float* __restrict__ out) {
    const int b  = blockIdx.y;
    const int sc = blockIdx.z;              // 16 chunks of 128 over S
    const int tid = threadIdx.x;            // 256 threads x 4 cols = 1024
    __shared__ float ws[128];
    if (tid < 128) ws[tid] = out[BB * DD + (size_t)b * SS + sc * 128 + tid];
    __syncthreads();

    const float4* hb = (const float4*)(h + ((size_t)b * SS + sc * 128) * DD) + tid;
    float4 acc = make_float4(0.f, 0.f, 0.f, 0.f);
    #pragma unroll 8
    for (int s = 0; s < 128; s++) {
        float4 v = hb[(size_t)s * (DD / 4)];
        float w = ws[s];
        acc.x += v.x * w; acc.y += v.y * w; acc.z += v.z * w; acc.w += v.w * w;
    }
    float* o = out + (size_t)b * DD + tid * 4;
    atomicAdd(o + 0, acc.x);
    atomicAdd(o + 1, acc.y);
    atomicAdd(o + 2, acc.z);
    atomicAdd(o + 3, acc.w);
}

// ---------------------------------------------------------------------------
extern "C" void kernel_launch(void* const* d_in, const int* in_sizes, int n_in,
                              void* d_out, int out_size) {
    const float* h  = (const float*)d_in[0];
    const float* rs = (const float*)d_in[1];
    const float* W  = (const float*)d_in[2];
    const float* U  = (const float*)d_in[3];
    float* out = (float*)d_out;

    cudaFuncSetAttribute(gemm_score_kernel,
                         cudaFuncAttributeMaxDynamicSharedMemorySize, SMEM_DYN);

    prep_kernel<<<4096, 256>>>(W, U, rs, out);
    gemm_score_kernel<<<dim3(8, 512), 128, SMEM_DYN>>>(h, rs);
    softmax_kernel<<<BB, 256>>>(out);
    matched_kernel<<<dim3(1, BB, 16), 256>>>(h, out);
}